// round 9
// baseline (speedup 1.0000x reference)
#include <cuda_runtime.h>
#include <math.h>

#define BN 32
#define TN 4096
#define UN 256
#define NJ 1024
#define CL 8

// ---------------- static device scratch (no runtime allocation) -------------
__device__ float g_Zx[(size_t)TN * BN * NJ];   // [t*32+b][j] input projection
__device__ float g_Wp[512 * NJ];               // packed W: rows 0..255 s-part, 256..511 x-part; col j=g*256+u

// ---------------- helpers ----------------------------------------------------
__device__ __forceinline__ unsigned smem_u32(const void* p) {
    unsigned a;
    asm("{ .reg .u64 t; cvta.to.shared.u64 t, %1; cvt.u32.u64 %0, t; }"
        : "=r"(a) : "l"(p));
    return a;
}
__device__ __forceinline__ unsigned long long pk2(float v) {
    unsigned long long r; unsigned u = __float_as_uint(v);
    asm("mov.b64 %0, {%1, %1};" : "=l"(r) : "r"(u));
    return r;
}
__device__ __forceinline__ unsigned long long pack2(float lo, float hi) {
    unsigned long long r;
    asm("mov.b64 %0, {%1, %2};" : "=l"(r)
        : "r"(__float_as_uint(lo)), "r"(__float_as_uint(hi)));
    return r;
}
__device__ __forceinline__ unsigned long long fma2(unsigned long long a,
                                                   unsigned long long b,
                                                   unsigned long long c) {
    unsigned long long d;
    asm("fma.rn.f32x2 %0, %1, %2, %3;" : "=l"(d) : "l"(a), "l"(b), "l"(c));
    return d;
}
__device__ __forceinline__ float2 upk2(unsigned long long v) {
    unsigned lo, hi;
    asm("mov.b64 {%0, %1}, %2;" : "=r"(lo), "=r"(hi) : "l"(v));
    return make_float2(__uint_as_float(lo), __uint_as_float(hi));
}
__device__ __forceinline__ unsigned mapa_u32(unsigned local, unsigned rank) {
    unsigned r;
    asm("mapa.shared::cluster.u32 %0, %1, %2;" : "=r"(r) : "r"(local), "r"(rank));
    return r;
}
__device__ __forceinline__ void mbar_init(unsigned addr, unsigned cnt) {
    asm volatile("mbarrier.init.shared.b64 [%0], %1;" :: "r"(addr), "r"(cnt) : "memory");
}
__device__ __forceinline__ void mbar_arrive_rel_cluster(unsigned addr) {
    asm volatile("mbarrier.arrive.release.cluster.shared::cluster.b64 _, [%0];"
                 :: "r"(addr) : "memory");
}
// CTA-scope acquire wait: avoids cluster-scope fence (CCTL.IVALL L1 flush).
// Cross-CTA visibility is carried by the producers' release.cluster arrives;
// state data lives in SMEM (uncached), local ordering by the acquire.cta.
__device__ __forceinline__ void mbar_wait_cta(unsigned addr, unsigned parity) {
    asm volatile(
        "{\n\t"
        ".reg .pred P;\n\t"
        "WL_%=:\n\t"
        "mbarrier.try_wait.parity.acquire.cta.shared::cta.b64 P, [%0], %1, 0x989680;\n\t"
        "@!P bra WL_%=;\n\t"
        "}"
        :: "r"(addr), "r"(parity) : "memory");
}
__device__ __forceinline__ void st_cluster_v4(unsigned addr, float4 v) {
    asm volatile("st.shared::cluster.v4.f32 [%0], {%1, %2, %3, %4};"
                 :: "r"(addr), "f"(v.x), "f"(v.y), "f"(v.z), "f"(v.w) : "memory");
}
// unified gate nonlinearity: A + B / (1 + exp(s*z))
__device__ __forceinline__ float gatefn(float a, float A, float B) {
    float e = __expf(a);
    float r = __fdividef(B, 1.0f + e);
    return A + r;
}
__device__ __forceinline__ float tanh_fast(float z) {
    float e = __expf(2.0f * z);
    return 1.0f - __fdividef(2.0f, 1.0f + e);
}

// ---------------- alignment rotator (so ncu -s 5 lands on k_rec) ------------
__global__ void k_nop() {}

// ---------------- kernel 0: pack weights ------------------------------------
__global__ __launch_bounds__(256) void k_init(const float* __restrict__ Wf,
                                              const float* __restrict__ Wi,
                                              const float* __restrict__ Wc,
                                              const float* __restrict__ Wo) {
    int idx = blockIdx.x * blockDim.x + threadIdx.x;
    if (idx < 512 * 1024) {
        int k = idx >> 10, j = idx & 1023;
        int g = j >> 8,    u = j & 255;
        const float* W = (g == 0) ? Wf : (g == 1) ? Wi : (g == 2) ? Wc : Wo;
        g_Wp[idx] = W[k * 256 + u];
    }
}

// ---------------- kernel 1: input projection GEMM ---------------------------
__global__ __launch_bounds__(256) void k_gemm(const float* __restrict__ x) {
    __shared__ __align__(16) float As[16][64];
    __shared__ __align__(16) float Bs[16][64];

    const int tid = threadIdx.x;
    const int n0  = blockIdx.x * 64;
    const int m0  = blockIdx.y * 64;
    const int tm  = tid >> 4, tn = tid & 15;
    const int ar  = tid >> 2, akq = tid & 3;
    const int bkr = tid >> 4, bnq = tid & 15;

    const int m_glob = m0 + ar;
    const int bb = m_glob & 31, tt = m_glob >> 5;
    const float* arow = x + ((size_t)bb * TN + tt) * 256;

    unsigned long long a00=0, a01=0, a10=0, a11=0, a20=0, a21=0, a30=0, a31=0;

    float4 av = *(const float4*)(arow + akq * 4);
    float4 bv = *(const float4*)(g_Wp + (size_t)(256 + bkr) * NJ + n0 + bnq * 4);

    for (int k0 = 0; k0 < 256; k0 += 16) {
        __syncthreads();
        As[akq * 4 + 0][ar] = av.x;
        As[akq * 4 + 1][ar] = av.y;
        As[akq * 4 + 2][ar] = av.z;
        As[akq * 4 + 3][ar] = av.w;
        *(float4*)&Bs[bkr][bnq * 4] = bv;
        __syncthreads();

        if (k0 + 16 < 256) {
            av = *(const float4*)(arow + k0 + 16 + akq * 4);
            bv = *(const float4*)(g_Wp + (size_t)(256 + k0 + 16 + bkr) * NJ + n0 + bnq * 4);
        }
        #pragma unroll
        for (int kk = 0; kk < 16; kk++) {
            float4 a = *(const float4*)&As[kk][tm * 4];
            ulonglong2 w = *(const ulonglong2*)&Bs[kk][tn * 4];
            unsigned long long p;
            p = pk2(a.x); a00 = fma2(p, w.x, a00); a01 = fma2(p, w.y, a01);
            p = pk2(a.y); a10 = fma2(p, w.x, a10); a11 = fma2(p, w.y, a11);
            p = pk2(a.z); a20 = fma2(p, w.x, a20); a21 = fma2(p, w.y, a21);
            p = pk2(a.w); a30 = fma2(p, w.x, a30); a31 = fma2(p, w.y, a31);
        }
    }
    float2 lo, hi;
    lo = upk2(a00); hi = upk2(a01);
    *(float4*)(g_Zx + (size_t)(m0 + tm*4 + 0) * NJ + n0 + tn*4) = make_float4(lo.x, lo.y, hi.x, hi.y);
    lo = upk2(a10); hi = upk2(a11);
    *(float4*)(g_Zx + (size_t)(m0 + tm*4 + 1) * NJ + n0 + tn*4) = make_float4(lo.x, lo.y, hi.x, hi.y);
    lo = upk2(a20); hi = upk2(a21);
    *(float4*)(g_Zx + (size_t)(m0 + tm*4 + 2) * NJ + n0 + tn*4) = make_float4(lo.x, lo.y, hi.x, hi.y);
    lo = upk2(a30); hi = upk2(a31);
    *(float4*)(g_Zx + (size_t)(m0 + tm*4 + 3) * NJ + n0 + tn*4) = make_float4(lo.x, lo.y, hi.x, hi.y);
}

// ---------------- kernel 2: persistent recurrence ----------------------------
// 16 clusters x 8 CTAs; cluster owns batches {2c, 2c+1} = two INDEPENDENT
// chains, software-pipelined: phase(b0,t) then phase(b1,t). b0's DSMEM pushes
// propagate while b1 computes -> comm off the critical path.
// CTA rank r owns u-slice [r*32, r*32+32); weights in registers (shared by
// both chains). Warp w waits only on source w's barrier (k-slice match).

// one phase of one batch chain
#define PHASE(B, ZX, OUTP)                                                     \
    do {                                                                       \
        const int cur = t & 1;                                                 \
        if (t > 0) {                                                           \
            const int e = t - 1;                                               \
            mbar_wait_cta(mywait[B][e & 1], (unsigned)((e >> 1) & 1));         \
        }                                                                      \
        unsigned long long ac0=0, ac1=0, ac2=0, ac3=0;                         \
        const float4* Sp = (const float4*)&Ssm[B][cur][kbeg];                  \
        _Pragma("unroll")                                                      \
        for (int kq = 0; kq < 4; kq++) {                                       \
            float4 s4 = Sp[kq];                                                \
            unsigned long long p;                                              \
            p = pk2(s4.x);                                                     \
            ac0 = fma2(p, w[kq*4+0][0], ac0); ac1 = fma2(p, w[kq*4+0][1], ac1);\
            ac2 = fma2(p, w[kq*4+0][2], ac2); ac3 = fma2(p, w[kq*4+0][3], ac3);\
            p = pk2(s4.y);                                                     \
            ac0 = fma2(p, w[kq*4+1][0], ac0); ac1 = fma2(p, w[kq*4+1][1], ac1);\
            ac2 = fma2(p, w[kq*4+1][2], ac2); ac3 = fma2(p, w[kq*4+1][3], ac3);\
            p = pk2(s4.z);                                                     \
            ac0 = fma2(p, w[kq*4+2][0], ac0); ac1 = fma2(p, w[kq*4+2][1], ac1);\
            ac2 = fma2(p, w[kq*4+2][2], ac2); ac3 = fma2(p, w[kq*4+2][3], ac3);\
            p = pk2(s4.w);                                                     \
            ac0 = fma2(p, w[kq*4+3][0], ac0); ac1 = fma2(p, w[kq*4+3][1], ac1);\
            ac2 = fma2(p, w[kq*4+3][2], ac2); ac3 = fma2(p, w[kq*4+3][3], ac3);\
        }                                                                      \
        { float2 v;                                                            \
          v = upk2(ac0); Zsm[kg][jq +  0] = v.x; Zsm[kg][jq + 16] = v.y;       \
          v = upk2(ac1); Zsm[kg][jq + 32] = v.x; Zsm[kg][jq + 48] = v.y;       \
          v = upk2(ac2); Zsm[kg][jq + 64] = v.x; Zsm[kg][jq + 80] = v.y;       \
          v = upk2(ac3); Zsm[kg][jq + 96] = v.x; Zsm[kg][jq +112] = v.y; }     \
        __syncthreads();                                                       \
        if (tid < 128) {                                                       \
            float z = (ZX);                                                    \
            _Pragma("unroll")                                                  \
            for (int g = 0; g < 16; g++) z += Zsm[g][tid];                     \
            float v = gatefn(gS * z, gA, gB);                                  \
            const int base = lane & ~3;                                        \
            float fv = __shfl_sync(0xFFFFFFFFu, v, base + 0);                  \
            float iv = __shfl_sync(0xFFFFFFFFu, v, base + 1);                  \
            float gv = __shfl_sync(0xFFFFFFFFu, v, base + 2);                  \
            float ov = __shfl_sync(0xFFFFFFFFu, v, base + 3);                  \
            if ((tid & 3) == 0) {                                              \
                float s_old = Ssm[B][cur][u0 + uu];                            \
                float c  = iv * gv + fv * s_old;                               \
                float ct = tanh_fast(c);                                       \
                float h  = ov * ct;                                            \
                stg[uu] = ct;                                                  \
                (OUTP)[0]     = h;                                             \
                (OUTP)[c_off] = ct;                                            \
            }                                                                  \
        }                                                                      \
        __syncthreads();                                                       \
        if (t + 1 < TN && lane < 8) {                                          \
            float4 vv = *(const float4*)&stg[lane * 4];                        \
            st_cluster_v4(dstS + (unsigned)((B)*2048 + ((t+1)&1)*1024), vv);   \
            mbar_arrive_rel_cluster(rbarB + (unsigned)((B)*128 + (t&1)*64));   \
        }                                                                      \
    } while (0)

__global__ __launch_bounds__(256, 1) __cluster_dims__(CL, 1, 1)
void k_rec(float* __restrict__ out, const float* __restrict__ h0) {
    __shared__ __align__(16) float Ssm[2][2][256];            // [batch][buf][k]
    __shared__ __align__(16) float Zsm[16][144];              // padded: halves bank-disjoint
    __shared__ __align__(16) float stg[32];
    __shared__ __align__(8)  unsigned long long mbars[2][2][8];  // [batch][buf][src]

    const int tid  = threadIdx.x;
    const int lane = tid & 31;
    const int wid  = tid >> 5;
    unsigned r;
    asm("mov.u32 %0, %%cluster_ctarank;" : "=r"(r));
    const int team = blockIdx.x >> 3;
    const int b0   = team * 2;
    const int u0   = (int)r * 32;

    const int kg = tid >> 4, jq = tid & 15, kbeg = kg * 16;
    const int gg = tid & 3, uu = (tid >> 2) & 31;             // gate role (tid<128)
    const int jcol = gg * 256 + u0 + uu;
    const size_t c_off = (size_t)BN * TN * UN;

    if (tid < 32) mbar_init(smem_u32(&mbars[tid >> 4][(tid >> 3) & 1][tid & 7]), 8);

    // initial state (buf 0) for both chains
    Ssm[0][0][tid] = h0[(b0 + 0) * 256 + tid];
    Ssm[1][0][tid] = h0[(b0 + 1) * 256 + tid];

    // gate-fn constants (f,i,g: sigmoid; o: tanh)
    const float gA = (gg == 3) ? 1.0f : 0.0f;
    const float gB = (gg == 3) ? -2.0f : 1.0f;
    const float gS = (gg == 3) ? 2.0f : -1.0f;

    // weight tile -> registers (shared by both chains)
    unsigned long long w[16][4];
    #pragma unroll
    for (int k = 0; k < 16; k++) {
        const float* row = g_Wp + (size_t)(kbeg + k) * NJ;
        #pragma unroll
        for (int m = 0; m < 4; m++) {
            int jA = jq + 32 * m, jB = jA + 16;
            int cA = (jA & 3) * 256 + u0 + (jA >> 2);
            int cB = (jB & 3) * 256 + u0 + (jB >> 2);
            w[k][m] = pack2(__ldg(row + cA), __ldg(row + cB));
        }
    }

    // push precompute: warp w targets rank w
    unsigned dstS = 0, rbarB = 0;
    if (lane < 8) {
        unsigned local = smem_u32(&Ssm[0][0][u0]) + (unsigned)(lane * 16);
        dstS  = mapa_u32(local, (unsigned)wid);
        rbarB = mapa_u32(smem_u32(&mbars[0][0][r]), (unsigned)wid);
    }
    unsigned mywait[2][2];
    mywait[0][0] = smem_u32(&mbars[0][0][wid]);
    mywait[0][1] = smem_u32(&mbars[0][1][wid]);
    mywait[1][0] = smem_u32(&mbars[1][0][wid]);
    mywait[1][1] = smem_u32(&mbars[1][1][wid]);

    // per-step pointers
    const float* zx0p = g_Zx + (size_t)(b0 + 0) * NJ + jcol;
    const float* zx1p = g_Zx + (size_t)(b0 + 1) * NJ + jcol;
    float* outH0 = out + (size_t)(b0 + 0) * TN * UN + (u0 + uu);
    float* outH1 = out + (size_t)(b0 + 1) * TN * UN + (u0 + uu);

    __syncthreads();
    asm volatile("barrier.cluster.arrive.aligned;" ::: "memory");
    asm volatile("barrier.cluster.wait.aligned;" ::: "memory");

    for (int t = 0; t < TN; t++) {
        float zx0 = 0.0f, zx1 = 0.0f;
        if (tid < 128) { zx0 = __ldcg(zx0p); zx1 = __ldcg(zx1p); }
        zx0p += 32 * NJ; zx1p += 32 * NJ;

        PHASE(0, zx0, outH0);
        PHASE(1, zx1, outH1);

        outH0 += UN; outH1 += UN;
    }
}

// ---------------- launcher ---------------------------------------------------
extern "C" void kernel_launch(void* const* d_in, const int* in_sizes, int n_in,
                              void* d_out, int out_size) {
    const float* x  = (const float*)d_in[0];
    const float* h0 = (const float*)d_in[1];
    const float* Wf = (const float*)d_in[2];
    const float* Wi = (const float*)d_in[3];
    const float* Wc = (const float*)d_in[4];
    const float* Wo = (const float*)d_in[5];
    float* out = (float*)d_out;

    k_nop<<<1, 1>>>();
    k_init<<<2048, 256>>>(Wf, Wi, Wc, Wo);
    dim3 gg(NJ / 64, (TN * BN) / 64);   // (16, 2048)
    k_gemm<<<gg, 256>>>(x);
    k_rec<<<128, 256>>>(out, h0);
}

// round 10
// speedup vs baseline: 1.5775x; 1.5775x over previous
#include <cuda_runtime.h>
#include <math.h>

#define BN 32
#define TN 4096
#define UN 256
#define NJ 1024
#define CL 8

// ---------------- static device scratch (no runtime allocation) -------------
__device__ float g_Zx[(size_t)TN * BN * NJ];   // [t*32+b][j] input projection
__device__ float g_Wp[512 * NJ];               // packed W: rows 0..255 s-part, 256..511 x-part; col j=g*256+u

// ---------------- helpers ----------------------------------------------------
__device__ __forceinline__ unsigned smem_u32(const void* p) {
    unsigned a;
    asm("{ .reg .u64 t; cvta.to.shared.u64 t, %1; cvt.u32.u64 %0, t; }"
        : "=r"(a) : "l"(p));
    return a;
}
__device__ __forceinline__ unsigned long long pk2(float v) {
    unsigned long long r; unsigned u = __float_as_uint(v);
    asm("mov.b64 %0, {%1, %1};" : "=l"(r) : "r"(u));
    return r;
}
__device__ __forceinline__ unsigned long long pack2(float lo, float hi) {
    unsigned long long r;
    asm("mov.b64 %0, {%1, %2};" : "=l"(r)
        : "r"(__float_as_uint(lo)), "r"(__float_as_uint(hi)));
    return r;
}
__device__ __forceinline__ unsigned long long fma2(unsigned long long a,
                                                   unsigned long long b,
                                                   unsigned long long c) {
    unsigned long long d;
    asm("fma.rn.f32x2 %0, %1, %2, %3;" : "=l"(d) : "l"(a), "l"(b), "l"(c));
    return d;
}
__device__ __forceinline__ float2 upk2(unsigned long long v) {
    unsigned lo, hi;
    asm("mov.b64 {%0, %1}, %2;" : "=r"(lo), "=r"(hi) : "l"(v));
    return make_float2(__uint_as_float(lo), __uint_as_float(hi));
}
__device__ __forceinline__ unsigned mapa_u32(unsigned local, unsigned rank) {
    unsigned r;
    asm("mapa.shared::cluster.u32 %0, %1, %2;" : "=r"(r) : "r"(local), "r"(rank));
    return r;
}
__device__ __forceinline__ void mbar_init(unsigned addr, unsigned cnt) {
    asm volatile("mbarrier.init.shared.b64 [%0], %1;" :: "r"(addr), "r"(cnt) : "memory");
}
__device__ __forceinline__ void mbar_arrive_rel_cluster(unsigned addr) {
    asm volatile("mbarrier.arrive.release.cluster.shared::cluster.b64 _, [%0];"
                 :: "r"(addr) : "memory");
}
// R6-exact wait: cluster-scope acquire, tight poll, NO suspend-time hint.
__device__ __forceinline__ void mbar_wait_cluster(unsigned addr, unsigned parity) {
    asm volatile(
        "{\n\t"
        ".reg .pred P;\n\t"
        "WL_%=:\n\t"
        "mbarrier.try_wait.parity.acquire.cluster.shared::cta.b64 P, [%0], %1;\n\t"
        "@!P bra WL_%=;\n\t"
        "}"
        :: "r"(addr), "r"(parity) : "memory");
}
__device__ __forceinline__ void st_cluster_v4(unsigned addr, float4 v) {
    asm volatile("st.shared::cluster.v4.f32 [%0], {%1, %2, %3, %4};"
                 :: "r"(addr), "f"(v.x), "f"(v.y), "f"(v.z), "f"(v.w) : "memory");
}
// unified gate nonlinearity: A + B / (1 + exp(s*z))
__device__ __forceinline__ float gatefn(float a, float A, float B) {
    float e = __expf(a);
    float r = __fdividef(B, 1.0f + e);
    return A + r;
}
__device__ __forceinline__ float tanh_fast(float z) {
    float e = __expf(2.0f * z);
    return 1.0f - __fdividef(2.0f, 1.0f + e);
}

// ---------------- alignment rotator (so ncu -s 5 lands on k_rec) ------------
__global__ void k_nop() {}

// ---------------- kernel 0: pack weights ------------------------------------
__global__ __launch_bounds__(256) void k_init(const float* __restrict__ Wf,
                                              const float* __restrict__ Wi,
                                              const float* __restrict__ Wc,
                                              const float* __restrict__ Wo) {
    int idx = blockIdx.x * blockDim.x + threadIdx.x;
    if (idx < 512 * 1024) {
        int k = idx >> 10, j = idx & 1023;
        int g = j >> 8,    u = j & 255;
        const float* W = (g == 0) ? Wf : (g == 1) ? Wi : (g == 2) ? Wc : Wo;
        g_Wp[idx] = W[k * 256 + u];
    }
}

// ---------------- kernel 1: input projection GEMM ---------------------------
__global__ __launch_bounds__(256) void k_gemm(const float* __restrict__ x) {
    __shared__ __align__(16) float As[16][64];
    __shared__ __align__(16) float Bs[16][64];

    const int tid = threadIdx.x;
    const int n0  = blockIdx.x * 64;
    const int m0  = blockIdx.y * 64;
    const int tm  = tid >> 4, tn = tid & 15;
    const int ar  = tid >> 2, akq = tid & 3;
    const int bkr = tid >> 4, bnq = tid & 15;

    const int m_glob = m0 + ar;
    const int bb = m_glob & 31, tt = m_glob >> 5;
    const float* arow = x + ((size_t)bb * TN + tt) * 256;

    unsigned long long a00=0, a01=0, a10=0, a11=0, a20=0, a21=0, a30=0, a31=0;

    float4 av = *(const float4*)(arow + akq * 4);
    float4 bv = *(const float4*)(g_Wp + (size_t)(256 + bkr) * NJ + n0 + bnq * 4);

    for (int k0 = 0; k0 < 256; k0 += 16) {
        __syncthreads();
        As[akq * 4 + 0][ar] = av.x;
        As[akq * 4 + 1][ar] = av.y;
        As[akq * 4 + 2][ar] = av.z;
        As[akq * 4 + 3][ar] = av.w;
        *(float4*)&Bs[bkr][bnq * 4] = bv;
        __syncthreads();

        if (k0 + 16 < 256) {
            av = *(const float4*)(arow + k0 + 16 + akq * 4);
            bv = *(const float4*)(g_Wp + (size_t)(256 + k0 + 16 + bkr) * NJ + n0 + bnq * 4);
        }
        #pragma unroll
        for (int kk = 0; kk < 16; kk++) {
            float4 a = *(const float4*)&As[kk][tm * 4];
            ulonglong2 w = *(const ulonglong2*)&Bs[kk][tn * 4];
            unsigned long long p;
            p = pk2(a.x); a00 = fma2(p, w.x, a00); a01 = fma2(p, w.y, a01);
            p = pk2(a.y); a10 = fma2(p, w.x, a10); a11 = fma2(p, w.y, a11);
            p = pk2(a.z); a20 = fma2(p, w.x, a20); a21 = fma2(p, w.y, a21);
            p = pk2(a.w); a30 = fma2(p, w.x, a30); a31 = fma2(p, w.y, a31);
        }
    }
    float2 lo, hi;
    lo = upk2(a00); hi = upk2(a01);
    *(float4*)(g_Zx + (size_t)(m0 + tm*4 + 0) * NJ + n0 + tn*4) = make_float4(lo.x, lo.y, hi.x, hi.y);
    lo = upk2(a10); hi = upk2(a11);
    *(float4*)(g_Zx + (size_t)(m0 + tm*4 + 1) * NJ + n0 + tn*4) = make_float4(lo.x, lo.y, hi.x, hi.y);
    lo = upk2(a20); hi = upk2(a21);
    *(float4*)(g_Zx + (size_t)(m0 + tm*4 + 2) * NJ + n0 + tn*4) = make_float4(lo.x, lo.y, hi.x, hi.y);
    lo = upk2(a30); hi = upk2(a31);
    *(float4*)(g_Zx + (size_t)(m0 + tm*4 + 3) * NJ + n0 + tn*4) = make_float4(lo.x, lo.y, hi.x, hi.y);
}

// ---------------- kernel 2: persistent recurrence (clusters + DSMEM) --------
// R6 structure: 16 clusters x 8 CTAs; cluster owns batches {2c, 2c+1}; CTA
// rank r owns u-slice [r*32, r*32+32), weights in registers. Warp w waits only
// on source w's barrier (its k-slice == source w's u-slice).
// CHANGED vs R6 (single variable): push parallelized — warp w pushes the CTA's
// 64-float state slice to rank w (16 lanes x 1 coalesced float4, single-target)
// and every lane does arrive.release -> barrier count = 16.
__global__ __launch_bounds__(256, 1) __cluster_dims__(CL, 1, 1)
void k_rec(float* __restrict__ out, const float* __restrict__ h0) {
    __shared__ __align__(16) float Ssm[2][512];       // [parity][k*2 + b]
    __shared__ __align__(16) float Zsm[16][272];      // [kg][b*128 + jj], padded
    __shared__ __align__(16) float stg[64];           // [uu*2 + b]
    __shared__ __align__(8)  unsigned long long mbars[8];  // one per source rank

    const int tid  = threadIdx.x;
    const int lane = tid & 31;
    const int wid  = tid >> 5;
    unsigned r;
    asm("mov.u32 %0, %%cluster_ctarank;" : "=r"(r));
    const int team = blockIdx.x >> 3;
    const int b0   = team * 2;
    const int u0   = (int)r * 32;

    const int kg = tid >> 4, jq = tid & 15, kbeg = kg * 16;
    const int jj = tid & 127, bb = tid >> 7;     // reduce/gate role (zi == tid)
    const int gg = jj & 3,    uu = jj >> 2;
    const int jcol = gg * 256 + u0 + uu;
    const size_t c_off = (size_t)BN * TN * UN;

    if (tid < 8) mbar_init(smem_u32(&mbars[tid]), 16);

    // initial state for step 0
    Ssm[0][tid * 2 + 0] = h0[(b0 + 0) * 256 + tid];
    Ssm[0][tid * 2 + 1] = h0[(b0 + 1) * 256 + tid];

    // gate-fn constants (f,i,g: sigmoid; o: tanh)
    const float gA = (gg == 3) ? 1.0f : 0.0f;
    const float gB = (gg == 3) ? -2.0f : 1.0f;
    const float gS = (gg == 3) ? 2.0f : -1.0f;

    // weight tile -> registers: u64 m pairs cols (jq+32m, jq+32m+16)
    unsigned long long w[16][4];
    #pragma unroll
    for (int k = 0; k < 16; k++) {
        const float* row = g_Wp + (size_t)(kbeg + k) * NJ;
        #pragma unroll
        for (int m = 0; m < 4; m++) {
            int jA = jq + 32 * m, jB = jA + 16;
            int cA = (jA & 3) * 256 + u0 + (jA >> 2);
            int cB = (jB & 3) * 256 + u0 + (jB >> 2);
            w[k][m] = pack2(__ldg(row + cA), __ldg(row + cB));
        }
    }

    // push precompute: warp w targets rank w; lane < 16 stores one float4
    unsigned dstA = 0, rbar = 0;
    if (lane < 16) {
        unsigned local = smem_u32(&Ssm[0][u0 * 2]) + (unsigned)(lane * 16);
        dstA = mapa_u32(local, (unsigned)wid);
        rbar = mapa_u32(smem_u32(&mbars[r]), (unsigned)wid);
    }
    const unsigned mywait = smem_u32(&mbars[wid]);

    // per-step incremented pointers
    const float* zxp = g_Zx + (size_t)(b0 + bb) * NJ + jcol;     // += 32*NJ
    float* outH = out + (size_t)(b0 + bb) * TN * UN + (u0 + uu); // += UN

    __syncthreads();
    asm volatile("barrier.cluster.arrive.aligned;" ::: "memory");
    asm volatile("barrier.cluster.wait.aligned;" ::: "memory");

    for (int t = 0; t < TN; t++) {
        const int cur = t & 1;

        // prefetch input projection (independent of state)
        float zx = __ldcg(zxp);
        zxp += 32 * NJ;

        // warp-sliced wait: only this warp's source slice must have arrived
        if (t > 0) mbar_wait_cluster(mywait, (unsigned)((t - 1) & 1));

        // recurrent matmul: 16 k x 4 u64 x 2 batches, weights in registers
        unsigned long long acc[2][4] = {{0,0,0,0},{0,0,0,0}};
        const float2* Sp = (const float2*)&Ssm[cur][kbeg * 2];
        #pragma unroll
        for (int k = 0; k < 16; k++) {
            float2 s = Sp[k];
            unsigned long long p0 = pk2(s.x), p1 = pk2(s.y);
            #pragma unroll
            for (int m = 0; m < 4; m++) {
                acc[0][m] = fma2(p0, w[k][m], acc[0][m]);
                acc[1][m] = fma2(p1, w[k][m], acc[1][m]);
            }
        }
        // conflict-free partial stores (lane-consecutive STS.32)
        #pragma unroll
        for (int b = 0; b < 2; b++) {
            #pragma unroll
            for (int m = 0; m < 4; m++) {
                float2 v = upk2(acc[b][m]);
                Zsm[kg][b * 128 + jq + 32 * m]      = v.x;
                Zsm[kg][b * 128 + jq + 32 * m + 16] = v.y;
            }
        }

        __syncthreads();

        // reduce 16 k-partials + input projection
        float z = zx;
        #pragma unroll
        for (int g = 0; g < 16; g++) z += Zsm[g][bb * 128 + jj];

        // branch-free per-lane nonlinearity, gather 4 gates via shuffle
        float v = gatefn(gS * z, gA, gB);
        const int base = lane & ~3;
        float fv = __shfl_sync(0xFFFFFFFFu, v, base + 0);
        float iv = __shfl_sync(0xFFFFFFFFu, v, base + 1);
        float gv = __shfl_sync(0xFFFFFFFFu, v, base + 2);
        float ov = __shfl_sync(0xFFFFFFFFu, v, base + 3);

        if ((tid & 3) == 0) {
            float s_old = Ssm[cur][(u0 + uu) * 2 + bb];
            float c  = iv * gv + fv * s_old;
            float ct = tanh_fast(c);
            float h  = ov * ct;
            stg[uu * 2 + bb] = ct;
            outH[0]     = h;
            outH[c_off] = ct;
        }
        outH += UN;
        __syncthreads();

        // push: warp w -> rank w; 16 coalesced float4 stores, per-lane arrive
        if (t + 1 < TN && lane < 16) {
            float4 vv = *(const float4*)&stg[lane * 4];
            st_cluster_v4(dstA + (unsigned)(((t + 1) & 1) * 2048), vv);
            mbar_arrive_rel_cluster(rbar);
        }
    }
}

// ---------------- launcher ---------------------------------------------------
extern "C" void kernel_launch(void* const* d_in, const int* in_sizes, int n_in,
                              void* d_out, int out_size) {
    const float* x  = (const float*)d_in[0];
    const float* h0 = (const float*)d_in[1];
    const float* Wf = (const float*)d_in[2];
    const float* Wi = (const float*)d_in[3];
    const float* Wc = (const float*)d_in[4];
    const float* Wo = (const float*)d_in[5];
    float* out = (float*)d_out;

    k_nop<<<1, 1>>>();
    k_init<<<2048, 256>>>(Wf, Wi, Wc, Wo);
    dim3 gg(NJ / 64, (TN * BN) / 64);   // (16, 2048)
    k_gemm<<<gg, 256>>>(x);
    k_rec<<<128, 256>>>(out, h0);
}

// round 11
// speedup vs baseline: 1.8119x; 1.1486x over previous
#include <cuda_runtime.h>
#include <math.h>

#define BN 32
#define TN 4096
#define UN 256
#define NJ 1024
#define CL 8

// ---------------- static device scratch (no runtime allocation) -------------
// padded by one step row so the t+1 prefetch at t = TN-1 stays in bounds
__device__ float g_Zx[(size_t)(TN + 1) * BN * NJ];   // [t*32+b][j] input projection
__device__ float g_Wp[512 * NJ];                     // packed W: rows 0..255 s-part, 256..511 x-part; col j=g*256+u

// ---------------- helpers ----------------------------------------------------
__device__ __forceinline__ unsigned smem_u32(const void* p) {
    unsigned a;
    asm("{ .reg .u64 t; cvta.to.shared.u64 t, %1; cvt.u32.u64 %0, t; }"
        : "=r"(a) : "l"(p));
    return a;
}
__device__ __forceinline__ unsigned long long pk2(float v) {
    unsigned long long r; unsigned u = __float_as_uint(v);
    asm("mov.b64 %0, {%1, %1};" : "=l"(r) : "r"(u));
    return r;
}
__device__ __forceinline__ unsigned long long pack2(float lo, float hi) {
    unsigned long long r;
    asm("mov.b64 %0, {%1, %2};" : "=l"(r)
        : "r"(__float_as_uint(lo)), "r"(__float_as_uint(hi)));
    return r;
}
__device__ __forceinline__ unsigned long long fma2(unsigned long long a,
                                                   unsigned long long b,
                                                   unsigned long long c) {
    unsigned long long d;
    asm("fma.rn.f32x2 %0, %1, %2, %3;" : "=l"(d) : "l"(a), "l"(b), "l"(c));
    return d;
}
__device__ __forceinline__ float2 upk2(unsigned long long v) {
    unsigned lo, hi;
    asm("mov.b64 {%0, %1}, %2;" : "=r"(lo), "=r"(hi) : "l"(v));
    return make_float2(__uint_as_float(lo), __uint_as_float(hi));
}
__device__ __forceinline__ unsigned mapa_u32(unsigned local, unsigned rank) {
    unsigned r;
    asm("mapa.shared::cluster.u32 %0, %1, %2;" : "=r"(r) : "r"(local), "r"(rank));
    return r;
}
__device__ __forceinline__ void mbar_init(unsigned addr, unsigned cnt) {
    asm volatile("mbarrier.init.shared.b64 [%0], %1;" :: "r"(addr), "r"(cnt) : "memory");
}
__device__ __forceinline__ void mbar_expect_tx(unsigned addr, unsigned bytes) {
    asm volatile("mbarrier.arrive.expect_tx.shared.b64 _, [%0], %1;"
                 :: "r"(addr), "r"(bytes) : "memory");
}
// standard TMA-style wait: CTA-scope acquire; async-proxy writes are made
// visible by the mbarrier completion itself (complete_tx mechanism).
__device__ __forceinline__ void mbar_wait(unsigned addr, unsigned parity) {
    asm volatile(
        "{\n\t"
        ".reg .pred P;\n\t"
        "WL_%=:\n\t"
        "mbarrier.try_wait.parity.acquire.cta.shared::cta.b64 P, [%0], %1;\n\t"
        "@!P bra WL_%=;\n\t"
        "}"
        :: "r"(addr), "r"(parity) : "memory");
}
// async store to a cluster CTA's SMEM; completion bumps tx-count on the
// remote mbarrier (fire-and-forget on the source side).
__device__ __forceinline__ void st_async_v4(unsigned addr, float4 v, unsigned rbar) {
    asm volatile(
        "st.async.shared::cluster.mbarrier::complete_tx::bytes.v4.f32 "
        "[%0], {%1, %2, %3, %4}, [%5];"
        :: "r"(addr), "f"(v.x), "f"(v.y), "f"(v.z), "f"(v.w), "r"(rbar) : "memory");
}
// unified gate nonlinearity: A + B / (1 + exp(s*z))
__device__ __forceinline__ float gatefn(float a, float A, float B) {
    float e = __expf(a);
    float r = __fdividef(B, 1.0f + e);
    return A + r;
}
__device__ __forceinline__ float tanh_fast(float z) {
    float e = __expf(2.0f * z);
    return 1.0f - __fdividef(2.0f, 1.0f + e);
}

// ---------------- alignment rotator (so ncu -s 5 lands on k_rec) ------------
__global__ void k_nop() {}

// ---------------- kernel 0: pack weights ------------------------------------
__global__ __launch_bounds__(256) void k_init(const float* __restrict__ Wf,
                                              const float* __restrict__ Wi,
                                              const float* __restrict__ Wc,
                                              const float* __restrict__ Wo) {
    int idx = blockIdx.x * blockDim.x + threadIdx.x;
    if (idx < 512 * 1024) {
        int k = idx >> 10, j = idx & 1023;
        int g = j >> 8,    u = j & 255;
        const float* W = (g == 0) ? Wf : (g == 1) ? Wi : (g == 2) ? Wc : Wo;
        g_Wp[idx] = W[k * 256 + u];
    }
}

// ---------------- kernel 1: input projection GEMM ---------------------------
__global__ __launch_bounds__(256) void k_gemm(const float* __restrict__ x) {
    __shared__ __align__(16) float As[16][64];
    __shared__ __align__(16) float Bs[16][64];

    const int tid = threadIdx.x;
    const int n0  = blockIdx.x * 64;
    const int m0  = blockIdx.y * 64;
    const int tm  = tid >> 4, tn = tid & 15;
    const int ar  = tid >> 2, akq = tid & 3;
    const int bkr = tid >> 4, bnq = tid & 15;

    const int m_glob = m0 + ar;
    const int bb = m_glob & 31, tt = m_glob >> 5;
    const float* arow = x + ((size_t)bb * TN + tt) * 256;

    unsigned long long a00=0, a01=0, a10=0, a11=0, a20=0, a21=0, a30=0, a31=0;

    float4 av = *(const float4*)(arow + akq * 4);
    float4 bv = *(const float4*)(g_Wp + (size_t)(256 + bkr) * NJ + n0 + bnq * 4);

    for (int k0 = 0; k0 < 256; k0 += 16) {
        __syncthreads();
        As[akq * 4 + 0][ar] = av.x;
        As[akq * 4 + 1][ar] = av.y;
        As[akq * 4 + 2][ar] = av.z;
        As[akq * 4 + 3][ar] = av.w;
        *(float4*)&Bs[bkr][bnq * 4] = bv;
        __syncthreads();

        if (k0 + 16 < 256) {
            av = *(const float4*)(arow + k0 + 16 + akq * 4);
            bv = *(const float4*)(g_Wp + (size_t)(256 + k0 + 16 + bkr) * NJ + n0 + bnq * 4);
        }
        #pragma unroll
        for (int kk = 0; kk < 16; kk++) {
            float4 a = *(const float4*)&As[kk][tm * 4];
            ulonglong2 w = *(const ulonglong2*)&Bs[kk][tn * 4];
            unsigned long long p;
            p = pk2(a.x); a00 = fma2(p, w.x, a00); a01 = fma2(p, w.y, a01);
            p = pk2(a.y); a10 = fma2(p, w.x, a10); a11 = fma2(p, w.y, a11);
            p = pk2(a.z); a20 = fma2(p, w.x, a20); a21 = fma2(p, w.y, a21);
            p = pk2(a.w); a30 = fma2(p, w.x, a30); a31 = fma2(p, w.y, a31);
        }
    }
    float2 lo, hi;
    lo = upk2(a00); hi = upk2(a01);
    *(float4*)(g_Zx + (size_t)(m0 + tm*4 + 0) * NJ + n0 + tn*4) = make_float4(lo.x, lo.y, hi.x, hi.y);
    lo = upk2(a10); hi = upk2(a11);
    *(float4*)(g_Zx + (size_t)(m0 + tm*4 + 1) * NJ + n0 + tn*4) = make_float4(lo.x, lo.y, hi.x, hi.y);
    lo = upk2(a20); hi = upk2(a21);
    *(float4*)(g_Zx + (size_t)(m0 + tm*4 + 2) * NJ + n0 + tn*4) = make_float4(lo.x, lo.y, hi.x, hi.y);
    lo = upk2(a30); hi = upk2(a31);
    *(float4*)(g_Zx + (size_t)(m0 + tm*4 + 3) * NJ + n0 + tn*4) = make_float4(lo.x, lo.y, hi.x, hi.y);
}

// ---------------- kernel 2: persistent recurrence (clusters + st.async) -----
// R6 structure: 16 clusters x 8 CTAs; cluster owns batches {2c, 2c+1}; CTA
// rank r owns u-slice [r*32, r*32+32), weights in registers. Warp w waits only
// on source w's barrier (its k-slice == source w's u-slice).
// Push #p (end of step p): lane tid<8 fires 16 st.async v4 (256B) into rank
// tid's Ssm[(p+1)&1] with complete_tx on that rank's mbars[p&1][r] -- no
// release stall, no arrive flight. Consumer warp w: wait parity (p>>1)&1 on
// mbars[p&1][w], then lane0 re-arms expect_tx(256) for the barrier's next use.
__global__ __launch_bounds__(256, 1) __cluster_dims__(CL, 1, 1)
void k_rec(float* __restrict__ out, const float* __restrict__ h0) {
    __shared__ __align__(16) float Ssm[2][512];       // [parity][k*2 + b]
    __shared__ __align__(16) float Zsm[16][272];      // [kg][b*128 + jj], padded
    __shared__ __align__(16) float stg[64];           // [uu*2 + b]
    __shared__ __align__(8)  unsigned long long mbars[2][8];  // [set = p&1][source]

    const int tid  = threadIdx.x;
    const int lane = tid & 31;
    const int wid  = tid >> 5;
    unsigned r;
    asm("mov.u32 %0, %%cluster_ctarank;" : "=r"(r));
    const int team = blockIdx.x >> 3;
    const int b0   = team * 2;
    const int u0   = (int)r * 32;

    const int kg = tid >> 4, jq = tid & 15, kbeg = kg * 16;
    const int jj = tid & 127, bb = tid >> 7;     // reduce/gate role (zi == tid)
    const int gg = jj & 3,    uu = jj >> 2;
    const int jcol = gg * 256 + u0 + uu;
    const size_t c_off = (size_t)BN * TN * UN;

    if (tid < 16) mbar_init(smem_u32(&mbars[tid >> 3][tid & 7]), 1);

    // initial state for step 0
    Ssm[0][tid * 2 + 0] = h0[(b0 + 0) * 256 + tid];
    Ssm[0][tid * 2 + 1] = h0[(b0 + 1) * 256 + tid];

    // gate-fn constants (f,i,g: sigmoid; o: tanh)
    const float gA = (gg == 3) ? 1.0f : 0.0f;
    const float gB = (gg == 3) ? -2.0f : 1.0f;
    const float gS = (gg == 3) ? 2.0f : -1.0f;

    // weight tile -> registers: u64 m pairs cols (jq+32m, jq+32m+16)
    unsigned long long w[16][4];
    #pragma unroll
    for (int k = 0; k < 16; k++) {
        const float* row = g_Wp + (size_t)(kbeg + k) * NJ;
        #pragma unroll
        for (int m = 0; m < 4; m++) {
            int jA = jq + 32 * m, jB = jA + 16;
            int cA = (jA & 3) * 256 + u0 + (jA >> 2);
            int cB = (jB & 3) * 256 + u0 + (jB >> 2);
            w[k][m] = pack2(__ldg(row + cA), __ldg(row + cB));
        }
    }

    // push precompute (lane tid < 8 pushes the CTA's 64-float slice to rank tid)
    unsigned dstA = 0, rbar0 = 0, rbar1 = 0;
    if (tid < 8) {
        dstA  = mapa_u32(smem_u32(&Ssm[0][u0 * 2]), (unsigned)tid);
        rbar0 = mapa_u32(smem_u32(&mbars[0][r]), (unsigned)tid);
        rbar1 = mapa_u32(smem_u32(&mbars[1][r]), (unsigned)tid);
    }
    const unsigned mywait0 = smem_u32(&mbars[0][wid]);
    const unsigned mywait1 = smem_u32(&mbars[1][wid]);

    // pre-arm both barrier sets (phase 0 of each): 1 arrive + 256B expected.
    // Issued before the cluster barrier, so it precedes any remote st.async.
    if (lane == 0) {
        mbar_expect_tx(mywait0, 256);
        mbar_expect_tx(mywait1, 256);
    }

    // per-step incremented pointers
    const float* zxp = g_Zx + (size_t)(b0 + bb) * NJ + jcol;     // += 32*NJ
    float* outH = out + (size_t)(b0 + bb) * TN * UN + (u0 + uu); // += UN

    __syncthreads();
    asm volatile("barrier.cluster.arrive.aligned;" ::: "memory");
    asm volatile("barrier.cluster.wait.aligned;" ::: "memory");

    // software-pipelined input-projection value (one step ahead)
    float zx_cur = __ldcg(zxp);

    for (int t = 0; t < TN; t++) {
        const int cur = t & 1;

        // prefetch NEXT step's input projection (padded row keeps it in bounds)
        float zx_nxt = __ldcg(zxp + 32 * NJ);
        zxp += 32 * NJ;

        // warp-sliced wait on this warp's source slice (push #t-1)
        if (t > 0) {
            const int e = t - 1;
            const unsigned bar = (e & 1) ? mywait1 : mywait0;
            mbar_wait(bar, (unsigned)((e >> 1) & 1));
            // re-arm this barrier for its next use (push #t+1); precedes our
            // own push #t, which gates every source's push #t+1.
            if (lane == 0) mbar_expect_tx(bar, 256);
        }

        // recurrent matmul: 16 k x 4 u64 x 2 batches, weights in registers
        unsigned long long acc[2][4] = {{0,0,0,0},{0,0,0,0}};
        const float2* Sp = (const float2*)&Ssm[cur][kbeg * 2];
        #pragma unroll
        for (int k = 0; k < 16; k++) {
            float2 s = Sp[k];
            unsigned long long p0 = pk2(s.x), p1 = pk2(s.y);
            #pragma unroll
            for (int m = 0; m < 4; m++) {
                acc[0][m] = fma2(p0, w[k][m], acc[0][m]);
                acc[1][m] = fma2(p1, w[k][m], acc[1][m]);
            }
        }
        // conflict-free partial stores (lane-consecutive STS.32)
        #pragma unroll
        for (int b = 0; b < 2; b++) {
            #pragma unroll
            for (int m = 0; m < 4; m++) {
                float2 v = upk2(acc[b][m]);
                Zsm[kg][b * 128 + jq + 32 * m]      = v.x;
                Zsm[kg][b * 128 + jq + 32 * m + 16] = v.y;
            }
        }

        __syncthreads();

        // reduce 16 k-partials + input projection
        float z = zx_cur;
        #pragma unroll
        for (int g = 0; g < 16; g++) z += Zsm[g][bb * 128 + jj];
        zx_cur = zx_nxt;

        // branch-free per-lane nonlinearity, gather 4 gates via shuffle
        float v = gatefn(gS * z, gA, gB);
        const int base = lane & ~3;
        float fv = __shfl_sync(0xFFFFFFFFu, v, base + 0);
        float iv = __shfl_sync(0xFFFFFFFFu, v, base + 1);
        float gv = __shfl_sync(0xFFFFFFFFu, v, base + 2);
        float ov = __shfl_sync(0xFFFFFFFFu, v, base + 3);

        if ((tid & 3) == 0) {
            float s_old = Ssm[cur][(u0 + uu) * 2 + bb];
            float c  = iv * gv + fv * s_old;
            float ct = tanh_fast(c);
            float h  = ov * ct;
            stg[uu * 2 + bb] = ct;
            outH[0]     = h;
            outH[c_off] = ct;
        }
        outH += UN;
        __syncthreads();

        // push #t: fire-and-forget async stores; completion = tx at target
        if (t + 1 < TN && tid < 8) {
            const unsigned dst  = dstA + (unsigned)(((t + 1) & 1) * 2048);
            const unsigned rbar = (t & 1) ? rbar1 : rbar0;
            #pragma unroll
            for (int i2 = 0; i2 < 16; i2++) {
                float4 vv = *(const float4*)&stg[i2 * 4];
                st_async_v4(dst + i2 * 16, vv, rbar);
            }
        }
    }
}

// ---------------- launcher ---------------------------------------------------
extern "C" void kernel_launch(void* const* d_in, const int* in_sizes, int n_in,
                              void* d_out, int out_size) {
    const float* x  = (const float*)d_in[0];
    const float* h0 = (const float*)d_in[1];
    const float* Wf = (const float*)d_in[2];
    const float* Wi = (const float*)d_in[3];
    const float* Wc = (const float*)d_in[4];
    const float* Wo = (const float*)d_in[5];
    float* out = (float*)d_out;

    k_nop<<<1, 1>>>();
    k_init<<<2048, 256>>>(Wf, Wi, Wc, Wo);
    dim3 gg(NJ / 64, (TN * BN) / 64);   // (16, 2048)
    k_gemm<<<gg, 256>>>(x);
    k_rec<<<128, 256>>>(out, h0);
}

// round 12
// speedup vs baseline: 2.2821x; 1.2595x over previous
#include <cuda_runtime.h>
#include <math.h>

#define BN 32
#define TN 4096
#define UN 256
#define NJ 1024
#define CL 8

// ---------------- static device scratch (no runtime allocation) -------------
// padded by one step row so the t+1 prefetch at t = TN-1 stays in bounds
__device__ float g_Zx[(size_t)(TN + 1) * BN * NJ];   // [t*32+b][j] input projection
__device__ float g_Wp[512 * NJ];                     // packed W: rows 0..255 s-part, 256..511 x-part; col j=g*256+u

// ---------------- helpers ----------------------------------------------------
__device__ __forceinline__ unsigned smem_u32(const void* p) {
    unsigned a;
    asm("{ .reg .u64 t; cvta.to.shared.u64 t, %1; cvt.u32.u64 %0, t; }"
        : "=r"(a) : "l"(p));
    return a;
}
__device__ __forceinline__ unsigned long long pk2(float v) {
    unsigned long long r; unsigned u = __float_as_uint(v);
    asm("mov.b64 %0, {%1, %1};" : "=l"(r) : "r"(u));
    return r;
}
__device__ __forceinline__ unsigned long long pack2(float lo, float hi) {
    unsigned long long r;
    asm("mov.b64 %0, {%1, %2};" : "=l"(r)
        : "r"(__float_as_uint(lo)), "r"(__float_as_uint(hi)));
    return r;
}
__device__ __forceinline__ unsigned long long fma2(unsigned long long a,
                                                   unsigned long long b,
                                                   unsigned long long c) {
    unsigned long long d;
    asm("fma.rn.f32x2 %0, %1, %2, %3;" : "=l"(d) : "l"(a), "l"(b), "l"(c));
    return d;
}
__device__ __forceinline__ float2 upk2(unsigned long long v) {
    unsigned lo, hi;
    asm("mov.b64 {%0, %1}, %2;" : "=r"(lo), "=r"(hi) : "l"(v));
    return make_float2(__uint_as_float(lo), __uint_as_float(hi));
}
__device__ __forceinline__ unsigned mapa_u32(unsigned local, unsigned rank) {
    unsigned r;
    asm("mapa.shared::cluster.u32 %0, %1, %2;" : "=r"(r) : "r"(local), "r"(rank));
    return r;
}
__device__ __forceinline__ void mbar_init(unsigned addr, unsigned cnt) {
    asm volatile("mbarrier.init.shared.b64 [%0], %1;" :: "r"(addr), "r"(cnt) : "memory");
}
__device__ __forceinline__ void mbar_expect_tx(unsigned addr, unsigned bytes) {
    asm volatile("mbarrier.arrive.expect_tx.shared.b64 _, [%0], %1;"
                 :: "r"(addr), "r"(bytes) : "memory");
}
// TMA-style wait: CTA-scope acquire, tight poll, no suspend hint.
__device__ __forceinline__ void mbar_wait(unsigned addr, unsigned parity) {
    asm volatile(
        "{\n\t"
        ".reg .pred P;\n\t"
        "WL_%=:\n\t"
        "mbarrier.try_wait.parity.acquire.cta.shared::cta.b64 P, [%0], %1;\n\t"
        "@!P bra WL_%=;\n\t"
        "}"
        :: "r"(addr), "r"(parity) : "memory");
}
// scalar async store to a cluster CTA's SMEM, tx-accounted at remote mbarrier
__device__ __forceinline__ void st_async_f32(unsigned addr, float v, unsigned rbar) {
    asm volatile(
        "st.async.shared::cluster.mbarrier::complete_tx::bytes.f32 [%0], %1, [%2];"
        :: "r"(addr), "f"(v), "r"(rbar) : "memory");
}
// unified gate nonlinearity: A + B / (1 + exp(s*z))
__device__ __forceinline__ float gatefn(float a, float A, float B) {
    float e = __expf(a);
    float r = __fdividef(B, 1.0f + e);
    return A + r;
}
__device__ __forceinline__ float tanh_fast(float z) {
    float e = __expf(2.0f * z);
    return 1.0f - __fdividef(2.0f, 1.0f + e);
}

// ---------------- alignment rotator (so ncu -s 5 lands on k_rec) ------------
__global__ void k_nop() {}

// ---------------- kernel 0: pack weights ------------------------------------
__global__ __launch_bounds__(256) void k_init(const float* __restrict__ Wf,
                                              const float* __restrict__ Wi,
                                              const float* __restrict__ Wc,
                                              const float* __restrict__ Wo) {
    int idx = blockIdx.x * blockDim.x + threadIdx.x;
    if (idx < 512 * 1024) {
        int k = idx >> 10, j = idx & 1023;
        int g = j >> 8,    u = j & 255;
        const float* W = (g == 0) ? Wf : (g == 1) ? Wi : (g == 2) ? Wc : Wo;
        g_Wp[idx] = W[k * 256 + u];
    }
}

// ---------------- kernel 1: input projection GEMM ---------------------------
__global__ __launch_bounds__(256) void k_gemm(const float* __restrict__ x) {
    __shared__ __align__(16) float As[16][64];
    __shared__ __align__(16) float Bs[16][64];

    const int tid = threadIdx.x;
    const int n0  = blockIdx.x * 64;
    const int m0  = blockIdx.y * 64;
    const int tm  = tid >> 4, tn = tid & 15;
    const int ar  = tid >> 2, akq = tid & 3;
    const int bkr = tid >> 4, bnq = tid & 15;

    const int m_glob = m0 + ar;
    const int bb = m_glob & 31, tt = m_glob >> 5;
    const float* arow = x + ((size_t)bb * TN + tt) * 256;

    unsigned long long a00=0, a01=0, a10=0, a11=0, a20=0, a21=0, a30=0, a31=0;

    float4 av = *(const float4*)(arow + akq * 4);
    float4 bv = *(const float4*)(g_Wp + (size_t)(256 + bkr) * NJ + n0 + bnq * 4);

    for (int k0 = 0; k0 < 256; k0 += 16) {
        __syncthreads();
        As[akq * 4 + 0][ar] = av.x;
        As[akq * 4 + 1][ar] = av.y;
        As[akq * 4 + 2][ar] = av.z;
        As[akq * 4 + 3][ar] = av.w;
        *(float4*)&Bs[bkr][bnq * 4] = bv;
        __syncthreads();

        if (k0 + 16 < 256) {
            av = *(const float4*)(arow + k0 + 16 + akq * 4);
            bv = *(const float4*)(g_Wp + (size_t)(256 + k0 + 16 + bkr) * NJ + n0 + bnq * 4);
        }
        #pragma unroll
        for (int kk = 0; kk < 16; kk++) {
            float4 a = *(const float4*)&As[kk][tm * 4];
            ulonglong2 w = *(const ulonglong2*)&Bs[kk][tn * 4];
            unsigned long long p;
            p = pk2(a.x); a00 = fma2(p, w.x, a00); a01 = fma2(p, w.y, a01);
            p = pk2(a.y); a10 = fma2(p, w.x, a10); a11 = fma2(p, w.y, a11);
            p = pk2(a.z); a20 = fma2(p, w.x, a20); a21 = fma2(p, w.y, a21);
            p = pk2(a.w); a30 = fma2(p, w.x, a30); a31 = fma2(p, w.y, a31);
        }
    }
    float2 lo, hi;
    lo = upk2(a00); hi = upk2(a01);
    *(float4*)(g_Zx + (size_t)(m0 + tm*4 + 0) * NJ + n0 + tn*4) = make_float4(lo.x, lo.y, hi.x, hi.y);
    lo = upk2(a10); hi = upk2(a11);
    *(float4*)(g_Zx + (size_t)(m0 + tm*4 + 1) * NJ + n0 + tn*4) = make_float4(lo.x, lo.y, hi.x, hi.y);
    lo = upk2(a20); hi = upk2(a21);
    *(float4*)(g_Zx + (size_t)(m0 + tm*4 + 2) * NJ + n0 + tn*4) = make_float4(lo.x, lo.y, hi.x, hi.y);
    lo = upk2(a30); hi = upk2(a31);
    *(float4*)(g_Zx + (size_t)(m0 + tm*4 + 3) * NJ + n0 + tn*4) = make_float4(lo.x, lo.y, hi.x, hi.y);
}

// ---------------- kernel 2: persistent recurrence ----------------------------
// 16 clusters x 8 CTAs; cluster owns batches {2c,2c+1}; CTA rank r owns
// u-slice [r*32,r*32+32), weights in registers.
// Warp w owns k-slice [32w,32w+32) == u-slice of source w -> waits mbars[.][w].
// Push: each gate thread st.async's its own ct (4B) to all 8 CTAs right after
// computing it (64 thr x 4B = 256B per source per target). ONE syncthreads per
// step; Zsm double-buffered to cover the one-step warp skew.
__global__ __launch_bounds__(256, 1) __cluster_dims__(CL, 1, 1)
void k_rec(float* __restrict__ out, const float* __restrict__ h0) {
    __shared__ __align__(16) float Ssm[2][512];        // [parity][k*2 + b]
    __shared__ __align__(16) float Zsm[2][8][264];     // [parity][kg][b*128 + jj]
    __shared__ __align__(8)  unsigned long long mbars[2][8];  // [set = p&1][source]

    const int tid  = threadIdx.x;
    const int lane = tid & 31;
    const int wid  = tid >> 5;
    unsigned r;
    asm("mov.u32 %0, %%cluster_ctarank;" : "=r"(r));
    const int team = blockIdx.x >> 3;
    const int b0   = team * 2;
    const int u0   = (int)r * 32;

    const int jq = lane, kbeg = wid * 32;        // matmul: warp = k-slice
    const int jj = tid & 127, bb = tid >> 7;     // reduce/gate role
    const int gg = jj & 3,    uu = jj >> 2;
    const int jcol = gg * 256 + u0 + uu;
    const size_t c_off = (size_t)BN * TN * UN;

    if (tid < 16) mbar_init(smem_u32(&mbars[tid >> 3][tid & 7]), 1);

    // initial state for step 0
    Ssm[0][tid * 2 + 0] = h0[(b0 + 0) * 256 + tid];
    Ssm[0][tid * 2 + 1] = h0[(b0 + 1) * 256 + tid];

    // gate-fn constants (f,i,g: sigmoid; o: tanh)
    const float gA = (gg == 3) ? 1.0f : 0.0f;
    const float gB = (gg == 3) ? -2.0f : 1.0f;
    const float gS = (gg == 3) ? 2.0f : -1.0f;

    // weights -> registers: w[k][m] packs cols (jq+64m, jq+64m+32), k in slice
    unsigned long long w[32][2];
    #pragma unroll
    for (int k = 0; k < 32; k++) {
        const float* row = g_Wp + (size_t)(kbeg + k) * NJ;
        #pragma unroll
        for (int m = 0; m < 2; m++) {
            int jA = jq + 64 * m, jB = jA + 32;
            int cA = (jA & 3) * 256 + u0 + (jA >> 2);
            int cB = (jB & 3) * 256 + u0 + (jB >> 2);
            w[k][m] = pack2(__ldg(row + cA), __ldg(row + cB));
        }
    }

    // remote addressing: one mapa base per rank; offsets are rank-invariant
    const unsigned SsmB = smem_u32(&Ssm[0][0]);
    unsigned m0v[8];
    #pragma unroll
    for (int rk = 0; rk < 8; rk++) m0v[rk] = mapa_u32(SsmB, (unsigned)rk);
    const unsigned barDelta = smem_u32(&mbars[0][0]) - SsmB + (unsigned)r * 8;
    const unsigned pushOffB = (unsigned)(((u0 + uu) * 2 + bb) * 4);

    const unsigned mywait0 = smem_u32(&mbars[0][wid]);
    const unsigned mywait1 = smem_u32(&mbars[1][wid]);

    // pre-arm both barrier sets (before cluster barrier -> precedes any push)
    if (lane == 0) {
        mbar_expect_tx(mywait0, 256);
        mbar_expect_tx(mywait1, 256);
    }

    // per-step incremented pointers
    const float* zxp = g_Zx + (size_t)(b0 + bb) * NJ + jcol;     // += 32*NJ
    float* outH = out + (size_t)(b0 + bb) * TN * UN + (u0 + uu); // += UN

    __syncthreads();
    asm volatile("barrier.cluster.arrive.aligned;" ::: "memory");
    asm volatile("barrier.cluster.wait.aligned;" ::: "memory");

    float zx_cur = __ldcg(zxp);   // input projection, one step ahead

    for (int t = 0; t < TN; t++) {
        const int cur = t & 1;

        float zx_nxt = __ldcg(zxp + 32 * NJ);
        zxp += 32 * NJ;

        // warp-sliced wait on this warp's source slice (push #t-1), re-arm
        if (t > 0) {
            const int e = t - 1;
            const unsigned bar = (e & 1) ? mywait1 : mywait0;
            mbar_wait(bar, (unsigned)((e >> 1) & 1));
            if (lane == 0) mbar_expect_tx(bar, 256);
        }

        // recurrent matmul: 32 k x 2 u64 x 2 batches (16 broadcast float4 loads)
        unsigned long long a00=0, a01=0, a10=0, a11=0;
        const float4* Sp = (const float4*)&Ssm[cur][kbeg * 2];
        #pragma unroll
        for (int kq = 0; kq < 16; kq++) {
            float4 s4 = Sp[kq];    // (k=2kq: b0,b1), (k=2kq+1: b0,b1)
            unsigned long long p;
            p = pk2(s4.x); a00 = fma2(p, w[2*kq][0],   a00); a01 = fma2(p, w[2*kq][1],   a01);
            p = pk2(s4.y); a10 = fma2(p, w[2*kq][0],   a10); a11 = fma2(p, w[2*kq][1],   a11);
            p = pk2(s4.z); a00 = fma2(p, w[2*kq+1][0], a00); a01 = fma2(p, w[2*kq+1][1], a01);
            p = pk2(s4.w); a10 = fma2(p, w[2*kq+1][0], a10); a11 = fma2(p, w[2*kq+1][1], a11);
        }
        {
            float2 v;
            float* zr = &Zsm[cur][wid][0];
            v = upk2(a00); zr[      jq]      = v.x; zr[      jq + 32] = v.y;
            v = upk2(a01); zr[      jq + 64] = v.x; zr[      jq + 96] = v.y;
            v = upk2(a10); zr[128 + jq]      = v.x; zr[128 + jq + 32] = v.y;
            v = upk2(a11); zr[128 + jq + 64] = v.x; zr[128 + jq + 96] = v.y;
        }

        __syncthreads();   // the ONLY block sync per step

        // reduce 8 k-partials + input projection
        float z = zx_cur;
        #pragma unroll
        for (int g = 0; g < 8; g++) z += Zsm[cur][g][bb * 128 + jj];
        zx_cur = zx_nxt;

        // branch-free nonlinearity, gather 4 gates via shuffle
        float v = gatefn(gS * z, gA, gB);
        const int base = lane & ~3;
        float fv = __shfl_sync(0xFFFFFFFFu, v, base + 0);
        float iv = __shfl_sync(0xFFFFFFFFu, v, base + 1);
        float gv = __shfl_sync(0xFFFFFFFFu, v, base + 2);
        float ov = __shfl_sync(0xFFFFFFFFu, v, base + 3);

        if ((tid & 3) == 0) {
            float s_old = Ssm[cur][(u0 + uu) * 2 + bb];
            float c  = iv * gv + fv * s_old;
            float ct = tanh_fast(c);
            float h  = ov * ct;
            // push ct immediately: 8 async scalar stores, tx-accounted remotely
            if (t + 1 < TN) {
                const unsigned po = pushOffB + (unsigned)(((t + 1) & 1) * 2048);
                const unsigned bo = barDelta + (unsigned)((t & 1) * 64);
                #pragma unroll
                for (int rk = 0; rk < 8; rk++)
                    st_async_f32(m0v[rk] + po, ct, m0v[rk] + bo);
            }
            outH[0]     = h;
            outH[c_off] = ct;
        }
        outH += UN;
    }
}

// ---------------- launcher ---------------------------------------------------
extern "C" void kernel_launch(void* const* d_in, const int* in_sizes, int n_in,
                              void* d_out, int out_size) {
    const float* x  = (const float*)d_in[0];
    const float* h0 = (const float*)d_in[1];
    const float* Wf = (const float*)d_in[2];
    const float* Wi = (const float*)d_in[3];
    const float* Wc = (const float*)d_in[4];
    const float* Wo = (const float*)d_in[5];
    float* out = (float*)d_out;

    k_nop<<<1, 1>>>();
    k_init<<<2048, 256>>>(Wf, Wi, Wc, Wo);
    dim3 gg(NJ / 64, (TN * BN) / 64);   // (16, 2048)
    k_gemm<<<gg, 256>>>(x);
    k_rec<<<128, 256>>>(out, h0);
}